// round 16
// baseline (speedup 1.0000x reference)
#include <cuda_runtime.h>
#include <cuda_fp16.h>
#include <cstdint>

// Problem constants
#define BB 2
#define CIN 256
#define HH 96
#define WW 96
#define COUT 256
#define KK2 9
#define HW (HH*WW)                 // 9216
#define MTOT (BB*HW)               // 18432
#define KKTOT (KK2*CIN)            // 2304
#define NGRP 32
#define GCH (COUT/NGRP)            // 8
#define GELEMS (GCH*HW)            // 73728
#define NK16 (KKTOT/16)            // 144 k16 steps
#define NST64 (KKTOT/64)           // 36 BK=64 stages

// Scratch (static device memory)
__device__ __align__(128) float    g_off[BB*18*HW];             // offsets  [B,18,H,W]
__device__ __align__(128) float    g_xt[(size_t)MTOT*CIN];      // x in NHWC: [b*HW+pix][c]
__device__ __align__(128) uint32_t g_Wf16[NK16*16*32*4];        // B fp16 frag order [k16][ngpair][lane][4]
__device__ __align__(128) uint32_t g_OWf16[NK16*4*32*2];        // offset-conv B fp16 [k16][ng4][lane][2]
__device__ __align__(128) float    g_O[(size_t)MTOT*COUT];      // GEMM out (NHWC): [M, Cout]
__device__ __align__(128) float    g_stats[NGRP*BB*2];          // per (b,g): sum, sumsq

// ------------------------------------------------------------- helpers
__device__ __forceinline__ uint32_t pack2_f16(float a, float b) {
    __half2 p = __floats2half2_rn(a, b);
    return *reinterpret_cast<uint32_t*>(&p);
}

#define CP_ASYNC16(dst, src) \
    asm volatile("cp.async.cg.shared.global [%0], [%1], 16;" \
                 :: "r"((uint32_t)(dst)), "l"(__cvta_generic_to_global(src)) : "memory")
#define CP_COMMIT() asm volatile("cp.async.commit_group;" ::: "memory")
#define CP_WAIT0()  asm volatile("cp.async.wait_group 0;" ::: "memory")

__device__ __forceinline__ uint32_t smem_u32(const void* p) {
    uint32_t a;
    asm("{ .reg .u64 t; cvta.to.shared.u64 t, %1; cvt.u32.u64 %0, t; }"
        : "=r"(a) : "l"(p));
    return a;
}

#define MMA_F16(acc, a, b0, b1) \
    asm volatile("mma.sync.aligned.m16n8k16.row.col.f32.f16.f16.f32 " \
                 "{%0,%1,%2,%3},{%4,%5,%6,%7},{%8,%9},{%0,%1,%2,%3};" \
                 : "+f"((acc)[0]), "+f"((acc)[1]), "+f"((acc)[2]), "+f"((acc)[3]) \
                 : "r"((a)[0]), "r"((a)[1]), "r"((a)[2]), "r"((a)[3]), \
                   "r"(b0), "r"(b1))

// ---------------------------------------------------------------- NCHW -> NHWC transpose of x
__global__ __launch_bounds__(256) void transpose_kernel(const float* __restrict__ x) {
    __shared__ float tile[32][33];
    const int m0 = blockIdx.x * 32;      // 576
    const int c0 = blockIdx.y * 32;      // 8
    const int tid = threadIdx.x;
    const int lane = tid & 31, row = tid >> 5;
    const int b = m0 / HW;
    const int pix0 = m0 - b*HW;

#pragma unroll
    for (int r = 0; r < 4; r++) {
        int cl = row + r*8;
        tile[cl][lane] = x[(size_t)(b*CIN + c0 + cl)*HW + pix0 + lane];
    }
    __syncthreads();
#pragma unroll
    for (int r = 0; r < 4; r++) {
        int pl = row + r*8;
        g_xt[(size_t)(m0 + pl)*CIN + c0 + lane] = tile[lane][pl];
    }
}

// ---------------------------------------------------------------- main weight repack fp16 (+ stats zero)
__global__ void repack_w_kernel(const float* __restrict__ cw) {
    if (blockIdx.x == 0 && threadIdx.x < NGRP*BB*2) g_stats[threadIdx.x] = 0.f;
    int idx = blockIdx.x * 256 + threadIdx.x;   // over NK16*16*32*4 = 294912
    if (idx >= NK16*16*32*4) return;
    int w4   = idx & 3;
    int lane = (idx >> 2) & 31;
    int pr   = (idx >> 7) & 15;
    int k16  = idx >> 11;
    int ng = pr*2 + (w4 >> 1);
    int j  = w4 & 1;
    int kk0 = k16*16 + j*8 + 2*(lane & 3);
    int n   = ng*8 + (lane >> 2);
    int c0 = kk0 & 255, tap0 = kk0 >> 8;
    int kk1 = kk0 + 1;
    int c1 = kk1 & 255, tap1 = kk1 >> 8;
    float v0 = cw[(n*CIN + c0)*9 + tap0];
    float v1 = cw[(n*CIN + c1)*9 + tap1];
    g_Wf16[idx] = pack2_f16(v0, v1);
}

// ---------------------------------------------------------------- offset weight repack fp16
__global__ void repack_ow_kernel(const float* __restrict__ ow) {
    int idx = blockIdx.x * 256 + threadIdx.x;   // over NK16*4*32*2 = 36864
    if (idx >= NK16*4*32*2) return;
    int j    = idx & 1;
    int t    = idx >> 1;
    int lane = t & 31; t >>= 5;
    int ng   = t & 3;
    int k16  = t >> 2;
    int kk0 = k16*16 + j*8 + 2*(lane & 3);
    int n   = ng*8 + (lane >> 2);
    int c0 = kk0 & 255, tap0 = kk0 >> 8;
    int kk1 = kk0 + 1;
    int c1 = kk1 & 255, tap1 = kk1 >> 8;
    float v0 = (n < 18) ? ow[(n*CIN + c0)*9 + tap0] : 0.f;
    float v1 = (n < 18) ? ow[(n*CIN + c1)*9 + tap1] : 0.f;
    g_OWf16[idx] = pack2_f16(v0, v1);
}

// ---------------------------------------------------------------- offset conv as 1xFP16 GEMM, BK=64
// BM=64 (grid=288, 2 CTAs/SM), N=32 (18 real), K=2304, 36 stages of BK=64.
// 256 threads = 4(wm)x2(wn). 2-stage A+B; interleaved producer schedule.
__global__ __launch_bounds__(256, 2) void offset_gemm_kernel(const float* __restrict__ ob) {
    __shared__ __align__(16) char asmb[2][8192];   // A: [ks(4)][wm(4)][512B]
    __shared__ __align__(16) char bsmb[2][4096];   // B: [ks(4)][1KB]
    const int tid = threadIdx.x, lane = tid & 31, wid = tid >> 5;
    const int wm = wid & 3, wn = wid >> 2;
    const int m0 = blockIdx.x * 64;
    const int b = m0 / HW;

    float acc[2][4];
#pragma unroll
    for (int i = 0; i < 2; i++)
#pragma unroll
        for (int e = 0; e < 4; e++) acc[i][e] = 0.f;

    // producer identity: row m_l, ks = cgrp, 16 channels/stage (4 per g)
    const int m_l  = tid >> 2;          // 0..63
    const int cgrp = tid & 3;           // ks
    const int p_wm = m_l >> 4;
    const int p_px = (m_l >> 3) & 1;
    const int p_row = m_l & 7;
    const int mm = m0 + m_l;
    const int rem = mm - b*HW;
    const int h = rem / WW, w = rem - h*WW;

    int64_t gptr = 0;
    bool valid = false;
    auto tapParams = [&](int tap) {
        const int py = h - 1 + tap/3, pxx = w - 1 + tap%3;
        valid = (py >= 0) && (py < HH) && (pxx >= 0) && (pxx < WW);
        gptr = (int64_t)(b*HW + py*WW + pxx) * CIN;
    };

    float4 cv;
    auto loadG = [&](int g, int q1) {
        const int c0s = ((q1 & 3) << 6) + cgrp*16 + g*4;
        cv = valid ? *reinterpret_cast<const float4*>(g_xt + gptr + c0s)
                   : make_float4(0.f, 0.f, 0.f, 0.f);
    };

    auto stsG = [&](int g, int s) {
        const int jh = g >> 1, pg = g & 1;
        char* base = asmb[s] + cgrp*2048 + p_wm*512;
        const int woff = jh*8 + p_px*4;
        const int sl0 = p_row*4 + ((pg*2)     ^ (p_row & 3));
        const int sl1 = p_row*4 + ((pg*2 + 1) ^ (p_row & 3));
        *(uint32_t*)(base + sl0*16 + woff) = pack2_f16(cv.x, cv.y);
        *(uint32_t*)(base + sl1*16 + woff) = pack2_f16(cv.z, cv.w);
    };

    const uint32_t bsb = smem_u32(bsmb);
    auto issueB = [&](int s, int q) {
        CP_ASYNC16(bsb + s*4096 + tid*16, g_OWf16 + (size_t)q*1024 + tid*4);
    };

    const int lane_sw = lane ^ ((lane >> 2) & 3);

    auto mmaStep = [&](int p, int ks) {
        const char* ab = asmb[p] + ks*2048 + wm*512 + lane_sw*16;
        uint4 h4 = *reinterpret_cast<const uint4*>(ab);
        uint32_t ah[4] = {h4.x, h4.y, h4.z, h4.w};
        const char* bb = bsmb[p] + ks*1024 + lane*8;
#pragma unroll
        for (int ng = 0; ng < 2; ng++) {
            const int ngg = wn*2 + ng;
            uint2 bh = *reinterpret_cast<const uint2*>(bb + ngg*256);
            MMA_F16(acc[ng], ah, bh.x, bh.y);
        }
    };

    // prologue
    tapParams(0);
#pragma unroll
    for (int g = 0; g < 4; g++) { loadG(g, 0); stsG(g, 0); }
    issueB(0, 0); CP_COMMIT();

    for (int q = 0; q < NST64; q++) {
        CP_WAIT0();
        __syncthreads();
        const bool more = (q + 1 < NST64);
        if (more) { issueB((q + 1) & 1, q + 1); CP_COMMIT(); }
        if (more && (((q + 1) & 3) == 0)) tapParams((q + 1) >> 2);
        const int p = q & 1, s1 = (q + 1) & 1;

        if (more) loadG(0, q + 1);
        mmaStep(p, 0);
        if (more) { stsG(0, s1); loadG(1, q + 1); }
        mmaStep(p, 1);
        if (more) { stsG(1, s1); loadG(2, q + 1); }
        mmaStep(p, 2);
        if (more) { stsG(2, s1); loadG(3, q + 1); }
        mmaStep(p, 3);
        if (more) stsG(3, s1);
    }

    // epilogue: offsets + bias (n < 18)
    const int mrow = m0 + wm*16 + (lane >> 2);
#pragma unroll
    for (int ng = 0; ng < 2; ng++) {
#pragma unroll
        for (int e = 0; e < 2; e++) {
            const int n = (wn*2 + ng)*8 + 2*(lane & 3) + e;
            if (n < 18) {
                const float bias = ob[n];
#pragma unroll
                for (int px = 0; px < 2; px++) {
                    const int m = mrow + px*8;
                    const int pr = m - b*HW;
                    g_off[(b*18 + n)*HW + pr] = acc[ng][px*2 + e] + bias;
                }
            }
        }
    }
}

// ---------------------------------------------------------------- fused gather + 1xFP16 GEMM + GN partials, BK=64
// BM=128 (grid=144, 1 CTA/SM), BN=256, 36 stages of BK=64, 512 threads
// (16 warps: wm=wid&3, wn=wid>>2). Interleaved LDG/MMA/STS schedule; 2-stage A+B.
#define B_STAGE 32768
#define A_BASE  65536
#define A_STG   16384
#define SRED_OFF (A_BASE + 2*A_STG)          // 98304
#define SMEM_BYTES (SRED_OFF + 256)

__global__ __launch_bounds__(512, 1) void gemm_kernel() {
    extern __shared__ char smem[];
    float* sred = (float*)(smem + SRED_OFF);
    const uint32_t sb = smem_u32(smem);
    const int tid = threadIdx.x, lane = tid & 31, wid = tid >> 5;
    const int wm = wid & 3, wn = wid >> 2;
    const int m0 = blockIdx.x * 128;
    const int b = m0 / HW;

    if (tid < 64) sred[tid] = 0.f;

    float acc[2][8][4];
#pragma unroll
    for (int i = 0; i < 2; i++)
#pragma unroll
        for (int j = 0; j < 8; j++)
#pragma unroll
            for (int e = 0; e < 4; e++) acc[i][j][e] = 0.f;

    // ---- producer identity: row m_l, ks = cgrp, 16 ch/stage (4 per g) ----
    const int m_l  = tid >> 2;                 // 0..127
    const int cgrp = tid & 3;                  // ks
    const int p_wm = (m_l >> 5) & 3;
    const int p_mt = (m_l >> 4) & 1;
    const int p_px = (m_l >> 3) & 1;
    const int p_row = m_l & 7;
    const int mm = m0 + m_l;
    const int rem = mm - b*HW;
    const int h = rem / WW, w = rem - h*WW;

    uint32_t gib[4];
    float    gw[4];

    auto tapParams = [&](int tap) {
        const int obidx = ((b*18 + 2*tap)*HH + h)*WW + w;
        const float dy = g_off[obidx];
        const float dx = g_off[obidx + HW];
        const float sy = (float)(h - 1 + tap/3) + dy;
        const float sx = (float)(w - 1 + tap%3) + dx;
        const float y0f = floorf(sy), x0f = floorf(sx);
        const float fy = sy - y0f, fx = sx - x0f;
        const int y0 = (int)y0f, x0 = (int)x0f;
        const int y1 = y0 + 1,  x1 = x0 + 1;
        const bool vy0 = (y0 >= 0) && (y0 < HH), vy1 = (y1 >= 0) && (y1 < HH);
        const bool vx0 = (x0 >= 0) && (x0 < WW), vx1 = (x1 >= 0) && (x1 < WW);
        gw[0] = (vy0 && vx0) ? (1.f-fy)*(1.f-fx) : 0.f;
        gw[1] = (vy0 && vx1) ? (1.f-fy)*fx       : 0.f;
        gw[2] = (vy1 && vx0) ? fy*(1.f-fx)       : 0.f;
        gw[3] = (vy1 && vx1) ? fy*fx             : 0.f;
        const int cy0 = min(max(y0,0),HH-1), cy1 = min(max(y1,0),HH-1);
        const int cx0 = min(max(x0,0),WW-1), cx1 = min(max(x1,0),WW-1);
        gib[0] = (uint32_t)(b*HW + cy0*WW+cx0) * CIN;
        gib[1] = (uint32_t)(b*HW + cy0*WW+cx1) * CIN;
        gib[2] = (uint32_t)(b*HW + cy1*WW+cx0) * CIN;
        gib[3] = (uint32_t)(b*HW + cy1*WW+cx1) * CIN;
    };

    float4 cv[4];
    auto loadG = [&](int g, int q1) {
        const int cg = ((q1 & 3) << 6) + cgrp*16 + g*4;
#pragma unroll
        for (int c = 0; c < 4; c++)
            cv[c] = *reinterpret_cast<const float4*>(g_xt + (size_t)gib[c] + cg);
    };

    auto stsG = [&](int g, int s) {
        float v0 = gw[0]*cv[0].x + gw[1]*cv[1].x + gw[2]*cv[2].x + gw[3]*cv[3].x;
        float v1 = gw[0]*cv[0].y + gw[1]*cv[1].y + gw[2]*cv[2].y + gw[3]*cv[3].y;
        float v2 = gw[0]*cv[0].z + gw[1]*cv[1].z + gw[2]*cv[2].z + gw[3]*cv[3].z;
        float v3 = gw[0]*cv[0].w + gw[1]*cv[1].w + gw[2]*cv[2].w + gw[3]*cv[3].w;
        const int jh = g >> 1, pg = g & 1;
        char* base = smem + A_BASE + s*A_STG + cgrp*4096 + p_wm*1024 + p_mt*512;
        const int woff = jh*8 + p_px*4;
        const int sl0 = p_row*4 + ((pg*2)     ^ (p_row & 3));
        const int sl1 = p_row*4 + ((pg*2 + 1) ^ (p_row & 3));
        *(uint32_t*)(base + sl0*16 + woff) = pack2_f16(v0, v1);
        *(uint32_t*)(base + sl1*16 + woff) = pack2_f16(v2, v3);
    };

    auto issueB = [&](int s, int q) {
        const uint32_t* srcH = g_Wf16 + (size_t)q * 8192;
        const uint32_t dH = sb + s*B_STAGE + tid*16;
#pragma unroll
        for (int j = 0; j < 4; j++)
            CP_ASYNC16(dH + j*8192, srcH + tid*4 + j*2048);
    };

    const int lane_sw = lane ^ ((lane >> 2) & 3);

    auto mmaStep = [&](int p, int ks) {
        const char* ab = smem + A_BASE + p*A_STG + ks*4096 + wm*1024 + lane_sw*16;
        uint32_t ah[2][4];
#pragma unroll
        for (int mt = 0; mt < 2; mt++) {
            uint4 h4 = *reinterpret_cast<const uint4*>(ab + mt*512);
            ah[mt][0] = h4.x; ah[mt][1] = h4.y; ah[mt][2] = h4.z; ah[mt][3] = h4.w;
        }
        const char* bb = smem + p*B_STAGE + ks*8192 + lane*16;
#pragma unroll
        for (int ntp = 0; ntp < 4; ntp++) {
            uint4 bh = *reinterpret_cast<const uint4*>(bb + (wn*4 + ntp)*512);
#pragma unroll
            for (int mt = 0; mt < 2; mt++) {
                MMA_F16(acc[mt][ntp*2],     ah[mt], bh.x, bh.y);
                MMA_F16(acc[mt][ntp*2 + 1], ah[mt], bh.z, bh.w);
            }
        }
    };

    // prologue
    tapParams(0);
#pragma unroll
    for (int g = 0; g < 4; g++) { loadG(g, 0); stsG(g, 0); }
    issueB(0, 0); CP_COMMIT();

    for (int q = 0; q < NST64; q++) {
        CP_WAIT0();
        __syncthreads();
        const bool more = (q + 1 < NST64);
        if (more) { issueB((q + 1) & 1, q + 1); CP_COMMIT(); }
        if (more && (((q + 1) & 3) == 0)) tapParams((q + 1) >> 2);
        const int p = q & 1, s1 = (q + 1) & 1;

        if (more) loadG(0, q + 1);
        mmaStep(p, 0);
        if (more) { stsG(0, s1); loadG(1, q + 1); }
        mmaStep(p, 1);
        if (more) { stsG(1, s1); loadG(2, q + 1); }
        mmaStep(p, 2);
        if (more) { stsG(2, s1); loadG(3, q + 1); }
        mmaStep(p, 3);
        if (more) stsG(3, s1);
    }

    // Epilogue: write g_O (NHWC) + GN partial sums
    const int mrow = m0 + wm*32 + (lane >> 2);
#pragma unroll
    for (int nt = 0; nt < 8; nt++) {
        const int ng = wn*8 + nt;
        const int n = wn*64 + nt*8 + 2*(lane & 3);
        float s = 0.f, s2 = 0.f;
#pragma unroll
        for (int mt = 0; mt < 2; mt++) {
            float* a4 = acc[mt][nt];
            const int m1 = mrow + mt*16;
            *reinterpret_cast<float2*>(&g_O[(size_t)m1*COUT + n])       = make_float2(a4[0], a4[1]);
            *reinterpret_cast<float2*>(&g_O[(size_t)(m1 + 8)*COUT + n]) = make_float2(a4[2], a4[3]);
            s  += a4[0] + a4[1] + a4[2] + a4[3];
            s2 += a4[0]*a4[0] + a4[1]*a4[1] + a4[2]*a4[2] + a4[3]*a4[3];
        }
#pragma unroll
        for (int o = 16; o > 0; o >>= 1) {
            s  += __shfl_down_sync(0xFFFFFFFFu, s,  o);
            s2 += __shfl_down_sync(0xFFFFFFFFu, s2, o);
        }
        if (lane == 0) {
            atomicAdd(&sred[ng*2 + 0], s);
            atomicAdd(&sred[ng*2 + 1], s2);
        }
    }
    __syncthreads();
    if (tid < 64) atomicAdd(&g_stats[b*64 + tid], sred[tid]);
}

// ---------------------------------------------------------------- GN + ReLU + NHWC->NCHW (smem transpose)
__global__ void norm_kernel(float* __restrict__ out,
                            const float* __restrict__ gamma,
                            const float* __restrict__ beta) {
    __shared__ float tile[32][33];
    const int m0 = blockIdx.x * 32;
    const int o0 = blockIdx.y * 32;
    const int tid = threadIdx.x;            // 256
    const int lane = tid & 31, row = tid >> 5;
    const int b = m0 / HW;

    const int o = o0 + lane;
    const int g = o >> 3;
    float s  = g_stats[(b*NGRP + g)*2 + 0];
    float s2 = g_stats[(b*NGRP + g)*2 + 1];
    float mu  = s  * (1.f / (float)GELEMS);
    float var = s2 * (1.f / (float)GELEMS) - mu*mu;
    float scale = rsqrtf(var + 1e-5f) * gamma[o];
    float shift = beta[o] - mu * scale;

#pragma unroll
    for (int r = 0; r < 4; r++) {
        int ml = r*8 + row;
        float v = g_O[(size_t)(m0 + ml)*COUT + o];
        tile[ml][lane] = fmaxf(fmaf(v, scale, shift), 0.f);
    }
    __syncthreads();
#pragma unroll
    for (int r = 0; r < 4; r++) {
        int ol = r*8 + row;
        int m = m0 + lane;
        out[(size_t)(b*COUT + o0 + ol)*HW + (m - b*HW)] = tile[lane][ol];
    }
}

// ---------------------------------------------------------------- launch
extern "C" void kernel_launch(void* const* d_in, const int* in_sizes, int n_in,
                              void* d_out, int out_size) {
    const float* x     = (const float*)d_in[0];
    const float* off_w = (const float*)d_in[1];
    const float* off_b = (const float*)d_in[2];
    const float* cw    = (const float*)d_in[3];
    const float* gamma = (const float*)d_in[4];
    const float* beta  = (const float*)d_in[5];
    float* out = (float*)d_out;

    cudaFuncSetAttribute(gemm_kernel,
                         cudaFuncAttributeMaxDynamicSharedMemorySize, SMEM_BYTES);

    transpose_kernel<<<dim3(MTOT/32, CIN/32), 256>>>(x);
    repack_w_kernel<<<(NK16*16*32*4 + 255)/256, 256>>>(cw);
    repack_ow_kernel<<<(NK16*4*32*2 + 255)/256, 256>>>(off_w);
    offset_gemm_kernel<<<MTOT/64, 256>>>(off_b);
    gemm_kernel<<<MTOT/128, 512, SMEM_BYTES>>>();
    norm_kernel<<<dim3(MTOT/32, COUT/32), 256>>>(out, gamma, beta);
}

// round 17
// speedup vs baseline: 1.3660x; 1.3660x over previous
#include <cuda_runtime.h>
#include <cuda_fp16.h>
#include <cstdint>

// Problem constants
#define BB 2
#define CIN 256
#define HH 96
#define WW 96
#define COUT 256
#define KK2 9
#define HW (HH*WW)                 // 9216
#define MTOT (BB*HW)               // 18432
#define KKTOT (KK2*CIN)            // 2304
#define NGRP 32
#define GCH (COUT/NGRP)            // 8
#define GELEMS (GCH*HW)            // 73728
#define NK16 (KKTOT/16)            // 144 k16 steps
#define NST (KKTOT/32)             // 72 BK=32 stages

// Scratch (static device memory)
__device__ __align__(128) float    g_off[BB*18*HW];             // offsets  [B,18,H,W]
__device__ __align__(128) float    g_xt[(size_t)MTOT*CIN];      // x in NHWC: [b*HW+pix][c]
__device__ __align__(128) uint32_t g_Wf16[NK16*16*32*4];        // B fp16 frag order [k16][ngpair][lane][4]
__device__ __align__(128) uint32_t g_OWf16[NK16*4*32*2];        // offset-conv B fp16 [k16][ng4][lane][2]
__device__ __align__(128) float    g_O[(size_t)MTOT*COUT];      // GEMM out (NHWC): [M, Cout]
__device__ __align__(128) float    g_stats[NGRP*BB*2];          // per (b,g): sum, sumsq

// ------------------------------------------------------------- helpers
__device__ __forceinline__ uint32_t pack2_f16(float a, float b) {
    __half2 p = __floats2half2_rn(a, b);
    return *reinterpret_cast<uint32_t*>(&p);
}

#define CP_ASYNC16(dst, src) \
    asm volatile("cp.async.cg.shared.global [%0], [%1], 16;" \
                 :: "r"((uint32_t)(dst)), "l"(__cvta_generic_to_global(src)) : "memory")
#define CP_COMMIT() asm volatile("cp.async.commit_group;" ::: "memory")
#define CP_WAIT0()  asm volatile("cp.async.wait_group 0;" ::: "memory")

__device__ __forceinline__ uint32_t smem_u32(const void* p) {
    uint32_t a;
    asm("{ .reg .u64 t; cvta.to.shared.u64 t, %1; cvt.u32.u64 %0, t; }"
        : "=r"(a) : "l"(p));
    return a;
}

#define MMA_F16(acc, a, b0, b1) \
    asm volatile("mma.sync.aligned.m16n8k16.row.col.f32.f16.f16.f32 " \
                 "{%0,%1,%2,%3},{%4,%5,%6,%7},{%8,%9},{%0,%1,%2,%3};" \
                 : "+f"((acc)[0]), "+f"((acc)[1]), "+f"((acc)[2]), "+f"((acc)[3]) \
                 : "r"((a)[0]), "r"((a)[1]), "r"((a)[2]), "r"((a)[3]), \
                   "r"(b0), "r"(b1))

// ---------------------------------------------------------------- NCHW -> NHWC transpose of x
__global__ __launch_bounds__(256) void transpose_kernel(const float* __restrict__ x) {
    __shared__ float tile[32][33];
    const int m0 = blockIdx.x * 32;      // 576
    const int c0 = blockIdx.y * 32;      // 8
    const int tid = threadIdx.x;
    const int lane = tid & 31, row = tid >> 5;
    const int b = m0 / HW;
    const int pix0 = m0 - b*HW;

#pragma unroll
    for (int r = 0; r < 4; r++) {
        int cl = row + r*8;
        tile[cl][lane] = x[(size_t)(b*CIN + c0 + cl)*HW + pix0 + lane];
    }
    __syncthreads();
#pragma unroll
    for (int r = 0; r < 4; r++) {
        int pl = row + r*8;
        g_xt[(size_t)(m0 + pl)*CIN + c0 + lane] = tile[lane][pl];
    }
}

// ---------------------------------------------------------------- main weight repack fp16 (+ stats zero)
__global__ void repack_w_kernel(const float* __restrict__ cw) {
    if (blockIdx.x == 0 && threadIdx.x < NGRP*BB*2) g_stats[threadIdx.x] = 0.f;
    int idx = blockIdx.x * 256 + threadIdx.x;   // over NK16*16*32*4 = 294912
    if (idx >= NK16*16*32*4) return;
    int w4   = idx & 3;
    int lane = (idx >> 2) & 31;
    int pr   = (idx >> 7) & 15;
    int k16  = idx >> 11;
    int ng = pr*2 + (w4 >> 1);
    int j  = w4 & 1;
    int kk0 = k16*16 + j*8 + 2*(lane & 3);
    int n   = ng*8 + (lane >> 2);
    int c0 = kk0 & 255, tap0 = kk0 >> 8;
    int kk1 = kk0 + 1;
    int c1 = kk1 & 255, tap1 = kk1 >> 8;
    float v0 = cw[(n*CIN + c0)*9 + tap0];
    float v1 = cw[(n*CIN + c1)*9 + tap1];
    g_Wf16[idx] = pack2_f16(v0, v1);
}

// ---------------------------------------------------------------- offset weight repack fp16
__global__ void repack_ow_kernel(const float* __restrict__ ow) {
    int idx = blockIdx.x * 256 + threadIdx.x;   // over NK16*4*32*2 = 36864
    if (idx >= NK16*4*32*2) return;
    int j    = idx & 1;
    int t    = idx >> 1;
    int lane = t & 31; t >>= 5;
    int ng   = t & 3;
    int k16  = t >> 2;
    int kk0 = k16*16 + j*8 + 2*(lane & 3);
    int n   = ng*8 + (lane >> 2);
    int c0 = kk0 & 255, tap0 = kk0 >> 8;
    int kk1 = kk0 + 1;
    int c1 = kk1 & 255, tap1 = kk1 >> 8;
    float v0 = (n < 18) ? ow[(n*CIN + c0)*9 + tap0] : 0.f;
    float v1 = (n < 18) ? ow[(n*CIN + c1)*9 + tap1] : 0.f;
    g_OWf16[idx] = pack2_f16(v0, v1);
}

// ---------------------------------------------------------------- offset conv as 1xFP16 GEMM
// BM=64 (grid=288, 2 CTAs/SM), N=32 (18 real), K=2304, BK=32. 256 threads = 4(wm)x2(wn).
// 3-stage A ring (write-ahead-2); A single fp16; B single fp16.
__global__ __launch_bounds__(256, 2) void offset_gemm_kernel(const float* __restrict__ ob) {
    __shared__ __align__(16) char asmb[3][4096];   // A: [ks(2)][wm(4)][512B]
    __shared__ __align__(16) char bsmb[2][2048];   // B: fp16 2KB/stage
    const int tid = threadIdx.x, lane = tid & 31, wid = tid >> 5;
    const int wm = wid & 3, wn = wid >> 2;
    const int m0 = blockIdx.x * 64;
    const int b = m0 / HW;

    float acc[2][4];
#pragma unroll
    for (int i = 0; i < 2; i++)
#pragma unroll
        for (int e = 0; e < 4; e++) acc[i][e] = 0.f;

    // producer identity
    const int m_l  = tid >> 2;          // 0..63
    const int cgrp = tid & 3;           // 8 channels
    const int p_ks = cgrp >> 1, p_jh = cgrp & 1;
    const int p_wm = m_l >> 4;
    const int p_px = (m_l >> 3) & 1;
    const int p_row = m_l & 7;
    const int mm = m0 + m_l;
    const int rem = mm - b*HW;
    const int h = rem / WW, w = rem - h*WW;

    int64_t gptr = 0;
    bool valid = false;
    auto tapParams = [&](int tap) {
        const int py = h - 1 + tap/3, pxx = w - 1 + tap%3;
        valid = (py >= 0) && (py < HH) && (pxx >= 0) && (pxx < WW);
        gptr = (int64_t)(b*HW + py*WW + pxx) * CIN;
    };

    float4 cv[2];
    auto loadG = [&](int q1) {
        const int c0s = ((q1 & 7) << 5) + p_ks*16 + p_jh*8;
        if (valid) {
            cv[0] = *reinterpret_cast<const float4*>(g_xt + gptr + c0s);
            cv[1] = *reinterpret_cast<const float4*>(g_xt + gptr + c0s + 4);
        } else {
            cv[0] = make_float4(0.f, 0.f, 0.f, 0.f);
            cv[1] = make_float4(0.f, 0.f, 0.f, 0.f);
        }
    };

    auto stsG = [&](int s) {
        char* base = asmb[s] + p_ks*2048 + p_wm*512;
        const int woff = p_jh*8 + p_px*4;
#pragma unroll
        for (int f = 0; f < 2; f++) {
            const int sl0 = p_row*4 + ((f*2)     ^ (p_row & 3));
            const int sl1 = p_row*4 + ((f*2 + 1) ^ (p_row & 3));
            *(uint32_t*)(base + sl0*16 + woff) = pack2_f16(cv[f].x, cv[f].y);
            *(uint32_t*)(base + sl1*16 + woff) = pack2_f16(cv[f].z, cv[f].w);
        }
    };

    const uint32_t bsb = smem_u32(bsmb);
    auto issueB = [&](int s, int q) {
        if (tid < 128)
            CP_ASYNC16(bsb + s*2048 + tid*16, g_OWf16 + (size_t)q*512 + tid*4);
    };

    const int lane_sw = lane ^ ((lane >> 2) & 3);

    auto mmaStep = [&](int sa, int p, int ks) {
        const char* ab = asmb[sa] + ks*2048 + wm*512 + lane_sw*16;
        uint4 h4 = *reinterpret_cast<const uint4*>(ab);
        uint32_t ah[4] = {h4.x, h4.y, h4.z, h4.w};
        const char* bb = bsmb[p] + ks*1024 + lane*8;
#pragma unroll
        for (int ng = 0; ng < 2; ng++) {
            const int ngg = wn*2 + ng;
            uint2 bh = *reinterpret_cast<const uint2*>(bb + ngg*256);
            MMA_F16(acc[ng], ah, bh.x, bh.y);
        }
    };

    // prologue: produce stages 0 and 1
    tapParams(0);
    loadG(0); stsG(0);
    loadG(1); stsG(1);
    issueB(0, 0); CP_COMMIT();

    for (int q = 0; q < NST; q++) {
        const bool more  = (q + 1 < NST);
        const bool more2 = (q + 2 < NST);
        if (more2 && (((q + 2) & 7) == 0)) tapParams((q + 2) >> 3);
        if (more2) loadG(q + 2);
        CP_WAIT0();
        __syncthreads();
        if (more) { issueB((q + 1) & 1, q + 1); CP_COMMIT(); }
        const int sa = q % 3, p = q & 1;
        mmaStep(sa, p, 0);
        mmaStep(sa, p, 1);
        if (more2) stsG((q + 2) % 3);
    }

    // epilogue: offsets + bias (n < 18)
    const int mrow = m0 + wm*16 + (lane >> 2);
#pragma unroll
    for (int ng = 0; ng < 2; ng++) {
#pragma unroll
        for (int e = 0; e < 2; e++) {
            const int n = (wn*2 + ng)*8 + 2*(lane & 3) + e;
            if (n < 18) {
                const float bias = ob[n];
#pragma unroll
                for (int px = 0; px < 2; px++) {
                    const int m = mrow + px*8;
                    const int pr = m - b*HW;
                    g_off[(b*18 + n)*HW + pr] = acc[ng][px*2 + e] + bias;
                }
            }
        }
    }
}

// ---------------------------------------------------------------- fused gather + 1xFP16 GEMM + GN partials
// BM=128 (grid=144, 1 CTA/SM), BN=256, BK=32, 512 threads (16 warps: wm=wid&3, wn=wid>>2).
// A single fp16 (no split); B single fp16. LDG->MMA->STS split schedule; 2-stage A+B.
#define B_STAGE 16384
#define A_BASE  32768
#define A_STG   8192
#define SRED_OFF (A_BASE + 2*A_STG)          // 49152
#define SMEM_BYTES (SRED_OFF + 256)

__global__ __launch_bounds__(512, 1) void gemm_kernel() {
    extern __shared__ char smem[];
    float* sred = (float*)(smem + SRED_OFF);
    const uint32_t sb = smem_u32(smem);
    const int tid = threadIdx.x, lane = tid & 31, wid = tid >> 5;
    const int wm = wid & 3, wn = wid >> 2;
    const int m0 = blockIdx.x * 128;
    const int b = m0 / HW;

    if (tid < 64) sred[tid] = 0.f;

    float acc[2][8][4];
#pragma unroll
    for (int i = 0; i < 2; i++)
#pragma unroll
        for (int j = 0; j < 8; j++)
#pragma unroll
            for (int e = 0; e < 4; e++) acc[i][j][e] = 0.f;

    // ---- producer identity ----
    const int m_l  = tid >> 2;                 // 0..127
    const int cgrp = tid & 3;                  // channel group (8 ch)
    const int p_wm = (m_l >> 5) & 3;
    const int p_mt = (m_l >> 4) & 1;
    const int p_px = (m_l >> 3) & 1;
    const int p_row = m_l & 7;
    const int p_ks = cgrp >> 1, p_jh = cgrp & 1;
    const int mm = m0 + m_l;
    const int rem = mm - b*HW;
    const int h = rem / WW, w = rem - h*WW;

    uint32_t gib[4];
    float    gw[4];

    auto tapParams = [&](int tap) {
        const int obidx = ((b*18 + 2*tap)*HH + h)*WW + w;
        const float dy = g_off[obidx];
        const float dx = g_off[obidx + HW];
        const float sy = (float)(h - 1 + tap/3) + dy;
        const float sx = (float)(w - 1 + tap%3) + dx;
        const float y0f = floorf(sy), x0f = floorf(sx);
        const float fy = sy - y0f, fx = sx - x0f;
        const int y0 = (int)y0f, x0 = (int)x0f;
        const int y1 = y0 + 1,  x1 = x0 + 1;
        const bool vy0 = (y0 >= 0) && (y0 < HH), vy1 = (y1 >= 0) && (y1 < HH);
        const bool vx0 = (x0 >= 0) && (x0 < WW), vx1 = (x1 >= 0) && (x1 < WW);
        gw[0] = (vy0 && vx0) ? (1.f-fy)*(1.f-fx) : 0.f;
        gw[1] = (vy0 && vx1) ? (1.f-fy)*fx       : 0.f;
        gw[2] = (vy1 && vx0) ? fy*(1.f-fx)       : 0.f;
        gw[3] = (vy1 && vx1) ? fy*fx             : 0.f;
        const int cy0 = min(max(y0,0),HH-1), cy1 = min(max(y1,0),HH-1);
        const int cx0 = min(max(x0,0),WW-1), cx1 = min(max(x1,0),WW-1);
        gib[0] = (uint32_t)(b*HW + cy0*WW+cx0) * CIN;
        gib[1] = (uint32_t)(b*HW + cy0*WW+cx1) * CIN;
        gib[2] = (uint32_t)(b*HW + cy1*WW+cx0) * CIN;
        gib[3] = (uint32_t)(b*HW + cy1*WW+cx1) * CIN;
    };

    float4 cv[4];
    auto loadG = [&](int g, int q1) {
        const int cg = ((q1 & 7) << 5) + cgrp*8 + g*4;
#pragma unroll
        for (int c = 0; c < 4; c++)
            cv[c] = *reinterpret_cast<const float4*>(g_xt + (size_t)gib[c] + cg);
    };

    auto stsG = [&](int g, int s) {
        float v0 = gw[0]*cv[0].x + gw[1]*cv[1].x + gw[2]*cv[2].x + gw[3]*cv[3].x;
        float v1 = gw[0]*cv[0].y + gw[1]*cv[1].y + gw[2]*cv[2].y + gw[3]*cv[3].y;
        float v2 = gw[0]*cv[0].z + gw[1]*cv[1].z + gw[2]*cv[2].z + gw[3]*cv[3].z;
        float v3 = gw[0]*cv[0].w + gw[1]*cv[1].w + gw[2]*cv[2].w + gw[3]*cv[3].w;
        uint32_t hw0 = pack2_f16(v0, v1);
        uint32_t hw1 = pack2_f16(v2, v3);
        char* base = smem + A_BASE + s*A_STG + p_ks*4096 + p_wm*1024 + p_mt*512;
        const int woff = p_jh*8 + p_px*4;
        const int sl0 = p_row*4 + ((g*2)     ^ (p_row & 3));
        const int sl1 = p_row*4 + ((g*2 + 1) ^ (p_row & 3));
        *(uint32_t*)(base + sl0*16 + woff) = hw0;
        *(uint32_t*)(base + sl1*16 + woff) = hw1;
    };

    auto issueB = [&](int s, int q) {
        const uint32_t* srcH = g_Wf16 + (size_t)q * 4096;
        const uint32_t dH = sb + s*B_STAGE + tid*16;
#pragma unroll
        for (int j = 0; j < 2; j++)
            CP_ASYNC16(dH + j*8192, srcH + tid*4 + j*2048);
    };

    const int lane_sw = lane ^ ((lane >> 2) & 3);

    auto mmaStep = [&](int p, int ks) {
        const char* ab = smem + A_BASE + p*A_STG + ks*4096 + wm*1024 + lane_sw*16;
        uint32_t ah[2][4];
#pragma unroll
        for (int mt = 0; mt < 2; mt++) {
            uint4 h4 = *reinterpret_cast<const uint4*>(ab + mt*512);
            ah[mt][0] = h4.x; ah[mt][1] = h4.y; ah[mt][2] = h4.z; ah[mt][3] = h4.w;
        }
        const char* bb = smem + p*B_STAGE + ks*8192 + lane*16;
#pragma unroll
        for (int ntp = 0; ntp < 4; ntp++) {
            uint4 bh = *reinterpret_cast<const uint4*>(bb + (wn*4 + ntp)*512);
#pragma unroll
            for (int mt = 0; mt < 2; mt++) {
                MMA_F16(acc[mt][ntp*2],     ah[mt], bh.x, bh.y);
                MMA_F16(acc[mt][ntp*2 + 1], ah[mt], bh.z, bh.w);
            }
        }
    };

    // prologue
    tapParams(0);
    loadG(0, 0); stsG(0, 0);
    loadG(1, 0); stsG(1, 0);
    issueB(0, 0); CP_COMMIT();

    for (int q = 0; q < NST; q++) {
        CP_WAIT0();
        __syncthreads();
        const bool more = (q + 1 < NST);
        if (more) { issueB((q + 1) & 1, q + 1); CP_COMMIT(); }
        if (more && (((q + 1) & 7) == 0)) tapParams((q + 1) >> 3);
        const int p = q & 1;

        if (more) loadG(0, q + 1);
        mmaStep(p, 0);
        if (more) { stsG(0, (q + 1) & 1); loadG(1, q + 1); }
        mmaStep(p, 1);
        if (more) stsG(1, (q + 1) & 1);
    }

    // Epilogue: write g_O (NHWC) + GN partial sums
    const int mrow = m0 + wm*32 + (lane >> 2);
#pragma unroll
    for (int nt = 0; nt < 8; nt++) {
        const int ng = wn*8 + nt;
        const int n = wn*64 + nt*8 + 2*(lane & 3);
        float s = 0.f, s2 = 0.f;
#pragma unroll
        for (int mt = 0; mt < 2; mt++) {
            float* a4 = acc[mt][nt];
            const int m1 = mrow + mt*16;
            *reinterpret_cast<float2*>(&g_O[(size_t)m1*COUT + n])       = make_float2(a4[0], a4[1]);
            *reinterpret_cast<float2*>(&g_O[(size_t)(m1 + 8)*COUT + n]) = make_float2(a4[2], a4[3]);
            s  += a4[0] + a4[1] + a4[2] + a4[3];
            s2 += a4[0]*a4[0] + a4[1]*a4[1] + a4[2]*a4[2] + a4[3]*a4[3];
        }
#pragma unroll
        for (int o = 16; o > 0; o >>= 1) {
            s  += __shfl_down_sync(0xFFFFFFFFu, s,  o);
            s2 += __shfl_down_sync(0xFFFFFFFFu, s2, o);
        }
        if (lane == 0) {
            atomicAdd(&sred[ng*2 + 0], s);
            atomicAdd(&sred[ng*2 + 1], s2);
        }
    }
    __syncthreads();
    if (tid < 64) atomicAdd(&g_stats[b*64 + tid], sred[tid]);
}

// ---------------------------------------------------------------- GN + ReLU + NHWC->NCHW (smem transpose)
__global__ void norm_kernel(float* __restrict__ out,
                            const float* __restrict__ gamma,
                            const float* __restrict__ beta) {
    __shared__ float tile[32][33];
    const int m0 = blockIdx.x * 32;
    const int o0 = blockIdx.y * 32;
    const int tid = threadIdx.x;            // 256
    const int lane = tid & 31, row = tid >> 5;
    const int b = m0 / HW;

    const int o = o0 + lane;
    const int g = o >> 3;
    float s  = g_stats[(b*NGRP + g)*2 + 0];
    float s2 = g_stats[(b*NGRP + g)*2 + 1];
    float mu  = s  * (1.f / (float)GELEMS);
    float var = s2 * (1.f / (float)GELEMS) - mu*mu;
    float scale = rsqrtf(var + 1e-5f) * gamma[o];
    float shift = beta[o] - mu * scale;

#pragma unroll
    for (int r = 0; r < 4; r++) {
        int ml = r*8 + row;
        float v = g_O[(size_t)(m0 + ml)*COUT + o];
        tile[ml][lane] = fmaxf(fmaf(v, scale, shift), 0.f);
    }
    __syncthreads();
#pragma unroll
    for (int r = 0; r < 4; r++) {
        int ol = r*8 + row;
        int m = m0 + lane;
        out[(size_t)(b*COUT + o0 + ol)*HW + (m - b*HW)] = tile[lane][ol];
    }
}

// ---------------------------------------------------------------- launch
extern "C" void kernel_launch(void* const* d_in, const int* in_sizes, int n_in,
                              void* d_out, int out_size) {
    const float* x     = (const float*)d_in[0];
    const float* off_w = (const float*)d_in[1];
    const float* off_b = (const float*)d_in[2];
    const float* cw    = (const float*)d_in[3];
    const float* gamma = (const float*)d_in[4];
    const float* beta  = (const float*)d_in[5];
    float* out = (float*)d_out;

    cudaFuncSetAttribute(gemm_kernel,
                         cudaFuncAttributeMaxDynamicSharedMemorySize, SMEM_BYTES);

    transpose_kernel<<<dim3(MTOT/32, CIN/32), 256>>>(x);
    repack_w_kernel<<<(NK16*16*32*4 + 255)/256, 256>>>(cw);
    repack_ow_kernel<<<(NK16*4*32*2 + 255)/256, 256>>>(off_w);
    offset_gemm_kernel<<<MTOT/64, 256>>>(off_b);
    gemm_kernel<<<MTOT/128, 512, SMEM_BYTES>>>();
    norm_kernel<<<dim3(MTOT/32, COUT/32), 256>>>(out, gamma, beta);
}